// round 17
// baseline (speedup 1.0000x reference)
#include <cuda_runtime.h>
#include <math.h>

// Fixed shapes: features [16,512,768] f32, labels [16,512] i32. N = 8192.
#define H      768
#define H2     (H / 2)          // 384 float2 per row
#define NCLS   10
#define TPB    512
#define NBLK   256              // 2 blocks/SM co-resident
#define RPB    32               // rows per block (N = NBLK*RPB = 8192)
#define RPW    2                // rows per warp in phase A (16 warps * 2)
#define CH     (NCLS * H)       // 7680 floats
#define CH4    (CH / 4)         // 1920 float4
#define NREP   4                // replicated RED targets (cuts per-addr depth)
#define TEMPERATURE 0.07f
#define EPS    1e-12f

// Device scratch. Zero at module load; restored to zero by the last block
// every run (self-cleaning for graph replay).
__device__ float    g_cs_r[NREP * CH];   // replicated class sums (RED targets)
__device__ int      g_cnt_tot[NCLS];
__device__ unsigned g_done = 0;

// Vector reduction: one RED.F32x4 to global memory (sm_90+).
__device__ __forceinline__ void red_add_v4(float* addr, float4 v)
{
    asm volatile("red.global.add.v4.f32 [%0], {%1, %2, %3, %4};"
                 :: "l"(addr), "f"(v.x), "f"(v.y), "f"(v.z), "f"(v.w)
                 : "memory");
}

__global__ __launch_bounds__(TPB, 2) void supcon_all(
    const float* __restrict__ feat,
    const int*   __restrict__ labels,
    float*       __restrict__ out,
    int out_size, int N)
{
    __shared__ float acc[CH];       // 30720 B
    __shared__ float inv[RPB];
    __shared__ int   labs[RPB];
    __shared__ unsigned ticket_sh;
    __shared__ float sredA[16];
    __shared__ float sredP[16];
    __shared__ float loss_sh;

    const int tid  = threadIdx.x;
    const int lane = tid & 31;
    const int warp = tid >> 5;
    const int bid  = blockIdx.x;
    const int row0 = bid * RPB;

    for (int i = tid; i < CH; i += TPB) acc[i] = 0.0f;
    if (tid < RPB) {
        int l = labels[row0 + tid];
        labs[tid] = min(max(l, 0), NCLS - 1);
    }

    // ---- Phase A: each of 16 warps computes norms of its 2 rows ----
    #pragma unroll
    for (int rr = 0; rr < RPW; ++rr) {
        const int r = warp * RPW + rr;
        const float4* x4 = reinterpret_cast<const float4*>(
                               feat + (size_t)(row0 + r) * H);
        float4 v[6];
        #pragma unroll
        for (int j = 0; j < 6; ++j)          // 6 independent LDG.128
            v[j] = x4[j * 32 + lane];
        float ss = 0.0f;
        #pragma unroll
        for (int j = 0; j < 6; ++j)
            ss += v[j].x*v[j].x + v[j].y*v[j].y + v[j].z*v[j].z + v[j].w*v[j].w;
        #pragma unroll
        for (int o = 16; o > 0; o >>= 1)
            ss += __shfl_xor_sync(0xffffffffu, ss, o);
        if (lane == 0)
            inv[r] = 1.0f / fmaxf(sqrtf(ss), EPS);
    }
    __syncthreads();

    // ---- Phase B: owner-float2, 8 front-batched loads per round (MLP 8) ----
    if (tid < H2) {
        float2* ap = reinterpret_cast<float2*>(acc);
        #pragma unroll
        for (int r0 = 0; r0 < RPB; r0 += 8) {
            float2 v[8];
            #pragma unroll
            for (int j = 0; j < 8; ++j)      // 8 independent LDG.64 (L2-hot)
                v[j] = reinterpret_cast<const float2*>(
                           feat + (size_t)(row0 + r0 + j) * H)[tid];
            #pragma unroll
            for (int j = 0; j < 8; ++j) {    // RMWs to <=10 distinct smem addrs
                const float iv = inv[r0 + j];
                float2* a = ap + labs[r0 + j] * H2 + tid;
                float2 t = *a;
                t.x += v[j].x * iv;
                t.y += v[j].y * iv;
                *a = t;
            }
        }
    }
    __syncthreads();

    // ---- Flush: RED.F32x4 into replica (bid & 3) — 64 adds/addr ----
    {
        float* base = g_cs_r + (bid & (NREP - 1)) * CH;
        const float4* a4 = reinterpret_cast<const float4*>(acc);
        #pragma unroll
        for (int k = 0; k < 4; ++k) {
            const int i = k * TPB + tid;     // [0, 2048); CH4 = 1920
            if (i < CH4)
                red_add_v4(base + 4 * i, a4[i]);
        }
        if (tid < NCLS) {
            int c = 0;
            #pragma unroll
            for (int r = 0; r < RPB; ++r) c += (labs[r] == tid);
            if (c > 0) atomicAdd(&g_cnt_tot[tid], c);
        }
    }

    // ---- Last-block ticket (no spinning) ----
    __threadfence();
    __syncthreads();
    if (tid == 0) ticket_sh = atomicAdd(&g_done, 1u);
    __syncthreads();
    if (ticket_sh != NBLK - 1) return;
    __threadfence();   // acquire: all other blocks' REDs visible

    // ---- Epilogue (f32): sum replicas on the fly ----
    float p_all = 0.0f, p_pos = 0.0f;
    for (int h = tid; h < H; h += TPB) {
        float sh = 0.0f;
        #pragma unroll
        for (int c = 0; c < NCLS; ++c) {
            float vv = 0.0f;
            #pragma unroll
            for (int rep = 0; rep < NREP; ++rep)
                vv += g_cs_r[rep * CH + c * H + h];
            sh    += vv;
            p_pos += vv * vv;
        }
        p_all += sh * sh;
    }
    #pragma unroll
    for (int o = 16; o > 0; o >>= 1) {
        p_all += __shfl_xor_sync(0xffffffffu, p_all, o);
        p_pos += __shfl_xor_sync(0xffffffffu, p_pos, o);
    }
    if (lane == 0) { sredA[warp] = p_all; sredP[warp] = p_pos; }
    __syncthreads();

    if (tid == 0) {
        float A = 0.0f, P = 0.0f;
        #pragma unroll
        for (int w = 0; w < 16; ++w) { A += sredA[w]; P += sredP[w]; }
        float n_pos = 0.0f;
        #pragma unroll
        for (int c = 0; c < NCLS; ++c) {
            float nc = (float)g_cnt_tot[c];
            n_pos += nc * nc;
        }
        float Nf    = (float)N;
        float n_neg = Nf * Nf - n_pos;

        float pos_mean = (P / TEMPERATURE) / n_pos;
        float neg_mean = ((A - P) / TEMPERATURE) / n_neg;
        float d = neg_mean - pos_mean;
        loss_sh = (d > 0.0f) ? d + log1pf(expf(-d)) : log1pf(expf(d));
    }
    __syncthreads();
    for (int i = tid; i < out_size; i += TPB) out[i] = loss_sh;

    // Self-clean for the next graph replay.
    for (int i = tid; i < NREP * CH; i += TPB) g_cs_r[i] = 0.0f;
    if (tid < NCLS) g_cnt_tot[tid] = 0;
    if (tid == 0)   g_done = 0u;
}

// ---------------------------------------------------------------------------
extern "C" void kernel_launch(void* const* d_in, const int* in_sizes, int n_in,
                              void* d_out, int out_size)
{
    const float* feat   = (const float*)d_in[0];
    const int*   labels = (const int*)d_in[1];
    float*       out    = (float*)d_out;
    const int N = in_sizes[1];   // 8192

    supcon_all<<<NBLK, TPB>>>(feat, labels, out, out_size, N);
}